// round 13
// baseline (speedup 1.0000x reference)
#include <cuda_runtime.h>

#define NP 262144
#define GRIDW 256
#define NUM_CELLS (GRIDW*GRIDW)
#define KSLOT 32
#define CAP 32
#define MAXN 64
#define FULLM 0xffffffffu

// ---------------- scratch (device globals) ----------------------------------
__device__ float    g_partH[256];
__device__ float    g_partX[256];
__device__ float    g_partY[256];
__device__ int      g_cellCount[NUM_CELLS + 1];
__device__ float4   g_cellListP[NUM_CELLS * CAP];       // {bits(idx), x, y, pad}
__device__ int      g_tabCnt[NUM_CELLS + 1];
__device__ float4   g_tab[(NUM_CELLS + 1) * KSLOT];     // {bits(idx), x, y, pad}
__device__ float2   g_aux[NP];                          // {t = d2 threshold, rh = 1/h}
__device__ uint2    g_pcnt[NUM_CELLS];                  // 9 stencil counts, 6b each

// ------- kernel 1: zero counts + per-block partial reductions ---------------
__global__ void initRedK(const float* __restrict__ pos, const float* __restrict__ sup) {
    int tid = blockIdx.x * blockDim.x + threadIdx.x;
    for (int c = tid; c <= NUM_CELLS; c += gridDim.x * blockDim.x)
        g_cellCount[c] = 0;
    if (tid == 0) g_tabCnt[NUM_CELLS] = 0;   // sentinel cell: always empty

    __shared__ float sH[256], sX[256], sY[256];
    float h = 0.0f, x = __int_as_float(0x7f800000), y = __int_as_float(0x7f800000);
    for (int i = tid; i < NP; i += gridDim.x * blockDim.x) {
        h = fmaxf(h, sup[i]);
        float2 p = ((const float2*)pos)[i];
        x = fminf(x, p.x);
        y = fminf(y, p.y);
    }
    int t = threadIdx.x;
    sH[t] = h; sX[t] = x; sY[t] = y;
    __syncthreads();
    for (int s = 128; s > 0; s >>= 1) {
        if (t < s) {
            sH[t] = fmaxf(sH[t], sH[t + s]);
            sX[t] = fminf(sX[t], sX[t + s]);
            sY[t] = fminf(sY[t], sY[t + s]);
        }
        __syncthreads();
    }
    if (t == 0) {
        g_partH[blockIdx.x] = sH[0];
        g_partX[blockIdx.x] = sX[0];
        g_partY[blockIdx.x] = sY[0];
    }
}

// ------- kernel 2: combine partials + bin particles + per-particle aux ------
__global__ void binK(const float* __restrict__ pos, const float* __restrict__ sup) {
    __shared__ float sH[256], sX[256], sY[256];
    int t = threadIdx.x;
    sH[t] = g_partH[t]; sX[t] = g_partX[t]; sY[t] = g_partY[t];
    __syncthreads();
    for (int s = 128; s > 0; s >>= 1) {
        if (t < s) {
            sH[t] = fmaxf(sH[t], sH[t + s]);
            sX[t] = fminf(sX[t], sX[t + s]);
            sY[t] = fminf(sY[t], sY[t + s]);
        }
        __syncthreads();
    }
    float hM = sH[0];
    float qx = sX[0] - hM;
    float qy = sY[0] - hM;

    int i = blockIdx.x * blockDim.x + threadIdx.x;
    if (i >= NP) return;
    float2 p = ((const float2*)pos)[i];
    int ix = (int)ceilf((p.x - qx) / hM);
    int iy = (int)ceilf((p.y - qy) / hM);
    ix = min(max(ix, 0), GRIDW - 1);
    iy = min(max(iy, 0), GRIDW - 1);
    int lin = ix + GRIDW * iy;
    int slot = atomicAdd(&g_cellCount[lin], 1);
    if (slot < CAP)
        g_cellListP[lin * CAP + slot] = make_float4(__int_as_float(i), p.x, p.y, 0.0f);

    // ---- per-particle: t = largest float with fl(sqrt(t)) <= h  (exact) ----
    float h = sup[i];
    float u = __fmul_rn(h, h);
    if (__fsqrt_rn(u) > h) u = __int_as_float(__float_as_int(u) - 1);
    if (__fsqrt_rn(u) > h) u = __int_as_float(__float_as_int(u) - 1);
    if (__fsqrt_rn(u) > h) u = __int_as_float(__float_as_int(u) - 1);
    float un = __int_as_float(__float_as_int(u) + 1);
    if (__fsqrt_rn(un) <= h) {
        u = un; un = __int_as_float(__float_as_int(u) + 1);
        if (__fsqrt_rn(un) <= h) {
            u = un; un = __int_as_float(__float_as_int(u) + 1);
            if (__fsqrt_rn(un) <= h) u = un;
        }
    }
    g_aux[i] = make_float2(u, __frcp_rn(h));
}

// ------- kernel 3: warp-per-cell rank sort (gather-free) --------------------
__global__ void sortK() {
    int w = (blockIdx.x * blockDim.x + threadIdx.x) >> 5;
    if (w >= NUM_CELLS) return;
    int lane = threadIdx.x & 31;
    int cnt = g_cellCount[w];
    int m = min(cnt, KSLOT);
    float4 e = make_float4(0.f, 0.f, 0.f, 0.f);
    int idx = 0x7fffffff;
    if (lane < m) {
        e = g_cellListP[w * CAP + lane];
        idx = __float_as_int(e.x);
    }
    int rank = 0;
    for (int j = 0; j < m; j++) {
        int v = __shfl_sync(FULLM, idx, j);
        rank += (v < idx);
    }
    if (lane == 0) g_tabCnt[w] = m;
    if (lane < m) g_tab[w * KSLOT + rank] = e;
}

// ------- kernel 3b: pack stencil counts (6 bits x 9) -------------------------
__global__ void packK() {
    int c = blockIdx.x * blockDim.x + threadIdx.x;
    if (c >= NUM_CELLS) return;
    unsigned lo = 0, hi = 0;
#pragma unroll
    for (int o = 0; o < 9; o++) {
        int off = (o / 3 - 1) + GRIDW * (o % 3 - 1);
        int cc = min(max(c + off, 0), NUM_CELLS);
        unsigned m = (unsigned)g_tabCnt[cc];
        if (o < 5) lo |= m << (6 * o);
        else       hi |= m << (6 * (o - 5));
    }
    g_pcnt[c] = make_uint2(lo, hi);
}

__device__ __forceinline__ float sqrt_approx(float x) {
    float r;
    asm("sqrt.approx.f32 %0, %1;" : "=f"(r) : "f"(x));
    return r;
}

// routing: candidate t -> stencil cell index cc and prefix po (pure ALU)
__device__ __forceinline__ void route(int t, int w,
                                      int P1, int P2, int P3, int P4,
                                      int P5, int P6, int P7, int P8,
                                      int& cc, int& po) {
    int o = (t >= P1) + (t >= P2) + (t >= P3) + (t >= P4) +
            (t >= P5) + (t >= P6) + (t >= P7) + (t >= P8);
    int p = 0;
    p = (t >= P1) ? P1 : p;
    p = (t >= P2) ? P2 : p;
    p = (t >= P3) ? P3 : p;
    p = (t >= P4) ? P4 : p;
    p = (t >= P5) ? P5 : p;
    p = (t >= P6) ? P6 : p;
    p = (t >= P7) ? P7 : p;
    p = (t >= P8) ? P8 : p;
    po = p;
    int dxo = o / 3 - 1;
    int dyo = o % 3 - 1;
    cc = min(max(w + dxo + GRIDW * dyo, 0), NUM_CELLS);
}

// ------- kernel 4: warp-per-cell neighbor search -----------------------------
__global__ void searchK(float* __restrict__ out) {
    __shared__ float4 sQ[8][32];      // per-warp query records {px, py, tq, rh}
    __shared__ int    sQb[8][32];     // per-warp query rbase (qid << 6)

    int w = (blockIdx.x * blockDim.x + threadIdx.x) >> 5;   // warp id = cell
    if (w >= NUM_CELLS) return;
    int lane = threadIdx.x & 31;
    int wid = (threadIdx.x >> 5) & 7;
    unsigned below = (1u << lane) - 1u;

    // ---- stencil setup: one LDG.64 + pure ALU (no scan, no broadcasts) ----
    uint2 pc = g_pcnt[w];
    int m0 =  pc.x        & 63;
    int m1 = (pc.x >>  6) & 63;
    int m2 = (pc.x >> 12) & 63;
    int m3 = (pc.x >> 18) & 63;
    int m4 = (pc.x >> 24) & 63;
    int m5 =  pc.y        & 63;
    int m6 = (pc.y >>  6) & 63;
    int m7 = (pc.y >> 12) & 63;
    int m8 = (pc.y >> 18) & 63;

    int qcnt = m4;                    // center cell = this cell's queries
    if (qcnt == 0) return;

    int P1 = m0;
    int P2 = P1 + m1;
    int P3 = P2 + m2;
    int P4 = P3 + m3;
    int P5 = P4 + m4;
    int P6 = P5 + m5;
    int P7 = P6 + m6;
    int P8 = P7 + m7;
    int T  = P8 + m8;

    // ---- query data: load + stage into smem ----
    int qidl = 0;
    if (lane < qcnt) {
        float4 qe = g_cellListP[w * CAP + lane];
        qidl = __float_as_int(qe.x);
        float2 aux = __ldg(&g_aux[qidl]);     // parallel prefetch {t, 1/h}
        sQ[wid][lane] = make_float4(qe.y, qe.z, aux.x, aux.y);
        sQb[wid][lane] = qidl << 6;
    }
    __syncwarp();

    // ---- preload candidates (chunks 0,1 cover T <= 64) ----
    float4 e0 = make_float4(0.f, 0.f, 0.f, 0.f);
    float4 e1 = make_float4(0.f, 0.f, 0.f, 0.f);
    bool act0 = lane < T;
    {
        int cc, po;
        route(lane, w, P1, P2, P3, P4, P5, P6, P7, P8, cc, po);
        if (act0) e0 = g_tab[cc * KSLOT + (lane - po)];
    }
    bool act1 = (lane + 32) < T;
    if (T > 32) {
        int cc, po;
        route(lane + 32, w, P1, P2, P3, P4, P5, P6, P7, P8, cc, po);
        if (act1) e1 = g_tab[cc * KSLOT + (lane + 32 - po)];
    }
    float n0 = (float)__float_as_int(e0.x);
    float n1 = (float)__float_as_int(e1.x);

    float* outN = out;                              // (N, 64) neighbor indices
    float* outC = out + (size_t)NP * MAXN;          // (N,)    counts
    float* outR = outC + NP;                        // (N, 64) radial

    int myCnt = 0;                                  // this lane's query count

    // ---- per-query loop ----
    for (int q = 0; q < qcnt; q++) {
        float4 qd = sQ[wid][q];                     // LDS.128 broadcast
        int  rbase = sQb[wid][q];                   // LDS.32  broadcast
        float px = qd.x, py = qd.y, tq = qd.z, rh = qd.w;
        float* pN = outN + rbase;
        float* pR = outR + rbase;

        int cnt;
        // chunk 0 — compute always, stores predicated
        {
            float dx = __fsub_rn(e0.y, px);
            float dy = __fsub_rn(e0.z, py);
            float d2 = __fadd_rn(__fmul_rn(dx, dx), __fmul_rn(dy, dy));
            float rad = __fmul_rn(sqrt_approx(d2), rh);
            bool ok = act0 && (d2 <= tq);
            unsigned bal = __ballot_sync(FULLM, ok);
            int slot = __popc(bal & below);
            if (ok) {
                __stcs(&pN[slot], n0);
                __stcs(&pR[slot], rad);
            }
            cnt = __popc(bal);
        }
        // chunk 1
        if (T > 32) {
            float dx = __fsub_rn(e1.y, px);
            float dy = __fsub_rn(e1.z, py);
            float d2 = __fadd_rn(__fmul_rn(dx, dx), __fmul_rn(dy, dy));
            float rad = __fmul_rn(sqrt_approx(d2), rh);
            bool ok = act1 && (d2 <= tq);
            unsigned bal = __ballot_sync(FULLM, ok);
            int slot = cnt + __popc(bal & below);
            if (ok) {
                __stcs(&pN[slot], n1);
                __stcs(&pR[slot], rad);
            }
            cnt += __popc(bal);
        }
        // rare: T > 64
        for (int tb = 64; tb < T; tb += 32) {
            int t = tb + lane;
            bool act = t < T;
            int cc, po;
            route(t, w, P1, P2, P3, P4, P5, P6, P7, P8, cc, po);
            float nidx = 0.0f, d2 = 0.0f;
            if (act) {
                float4 e = g_tab[cc * KSLOT + (t - po)];
                float dx = __fsub_rn(e.y, px);
                float dy = __fsub_rn(e.z, py);
                d2 = __fadd_rn(__fmul_rn(dx, dx), __fmul_rn(dy, dy));
                nidx = (float)__float_as_int(e.x);
            }
            float rad = __fmul_rn(sqrt_approx(d2), rh);
            bool ok = act && (d2 <= tq);
            unsigned bal = __ballot_sync(FULLM, ok);
            int slot = cnt + __popc(bal & below);
            if (ok && slot < MAXN) {
                __stcs(&pN[slot], nidx);
                __stcs(&pR[slot], rad);
            }
            cnt += __popc(bal);
        }
        // tail fill: unrolled two predicated steps (tail length <= 64)
        int start = min(cnt, MAXN);
        int k0 = start + lane;
        if (k0 < MAXN) {
            __stcs(&pN[k0], -1.0f);
            __stcs(&pR[k0], 0.0f);
        }
        int k1 = k0 + 32;
        if (k1 < MAXN) {
            __stcs(&pN[k1], -1.0f);
            __stcs(&pR[k1], 0.0f);
        }
        if (q == lane) myCnt = cnt;                 // defer count store
    }
    if (lane < qcnt) __stcs(&outC[qidl], (float)myCnt);
}

// ---------------- launch ------------------------------------------------------
extern "C" void kernel_launch(void* const* d_in, const int* in_sizes, int n_in,
                              void* d_out, int out_size) {
    const float* pos = (const float*)d_in[0];   // (N, 2) float32
    const float* sup = (const float*)d_in[1];   // (N,)   float32
    float* out = (float*)d_out;

    initRedK<<<256, 256>>>(pos, sup);
    binK<<<NP / 256, 256>>>(pos, sup);
    sortK<<<(NUM_CELLS * 32) / 256, 256>>>();
    packK<<<NUM_CELLS / 256, 256>>>();
    searchK<<<(NUM_CELLS * 32) / 256, 256>>>(out);
}

// round 14
// speedup vs baseline: 1.2953x; 1.2953x over previous
#include <cuda_runtime.h>

#define NP 262144
#define GRIDW 256
#define NUM_CELLS (GRIDW*GRIDW)
#define KSLOT 32
#define CAP 32
#define MAXN 64
#define FULLM 0xffffffffu

// ---------------- scratch (device globals) ----------------------------------
__device__ float    g_partH[256];
__device__ float    g_partX[256];
__device__ float    g_partY[256];
__device__ int      g_cellCount[NUM_CELLS + 1];
__device__ float4   g_cellListP[NUM_CELLS * CAP];       // {bits(idx), x, y, pad}
__device__ int      g_tabCnt[NUM_CELLS + 1];
__device__ float4   g_tab[(NUM_CELLS + 1) * KSLOT];     // {bits(idx), x, y, pad}
__device__ float2   g_aux[NP];                          // {t = d2 threshold, rh = 1/h}

// ------- kernel 1: zero counts + per-block partial reductions ---------------
__global__ void initRedK(const float* __restrict__ pos, const float* __restrict__ sup) {
    int tid = blockIdx.x * blockDim.x + threadIdx.x;
    for (int c = tid; c <= NUM_CELLS; c += gridDim.x * blockDim.x)
        g_cellCount[c] = 0;
    if (tid == 0) g_tabCnt[NUM_CELLS] = 0;   // sentinel cell: always empty

    __shared__ float sH[256], sX[256], sY[256];
    float h = 0.0f, x = __int_as_float(0x7f800000), y = __int_as_float(0x7f800000);
    for (int i = tid; i < NP; i += gridDim.x * blockDim.x) {
        h = fmaxf(h, sup[i]);
        float2 p = ((const float2*)pos)[i];
        x = fminf(x, p.x);
        y = fminf(y, p.y);
    }
    int t = threadIdx.x;
    sH[t] = h; sX[t] = x; sY[t] = y;
    __syncthreads();
    for (int s = 128; s > 0; s >>= 1) {
        if (t < s) {
            sH[t] = fmaxf(sH[t], sH[t + s]);
            sX[t] = fminf(sX[t], sX[t + s]);
            sY[t] = fminf(sY[t], sY[t + s]);
        }
        __syncthreads();
    }
    if (t == 0) {
        g_partH[blockIdx.x] = sH[0];
        g_partX[blockIdx.x] = sX[0];
        g_partY[blockIdx.x] = sY[0];
    }
}

// ------- kernel 2: combine partials + bin particles + per-particle aux ------
__global__ void binK(const float* __restrict__ pos, const float* __restrict__ sup) {
    __shared__ float sH[256], sX[256], sY[256];
    int t = threadIdx.x;
    sH[t] = g_partH[t]; sX[t] = g_partX[t]; sY[t] = g_partY[t];
    __syncthreads();
    for (int s = 128; s > 0; s >>= 1) {
        if (t < s) {
            sH[t] = fmaxf(sH[t], sH[t + s]);
            sX[t] = fminf(sX[t], sX[t + s]);
            sY[t] = fminf(sY[t], sY[t + s]);
        }
        __syncthreads();
    }
    float hM = sH[0];
    float qx = sX[0] - hM;
    float qy = sY[0] - hM;

    int i = blockIdx.x * blockDim.x + threadIdx.x;
    if (i >= NP) return;
    float2 p = ((const float2*)pos)[i];
    int ix = (int)ceilf((p.x - qx) / hM);
    int iy = (int)ceilf((p.y - qy) / hM);
    ix = min(max(ix, 0), GRIDW - 1);
    iy = min(max(iy, 0), GRIDW - 1);
    int lin = ix + GRIDW * iy;
    int slot = atomicAdd(&g_cellCount[lin], 1);
    if (slot < CAP)
        g_cellListP[lin * CAP + slot] = make_float4(__int_as_float(i), p.x, p.y, 0.0f);

    // ---- per-particle: t = largest float with fl(sqrt(t)) <= h  (exact) ----
    float h = sup[i];
    float u = __fmul_rn(h, h);
    if (__fsqrt_rn(u) > h) u = __int_as_float(__float_as_int(u) - 1);
    if (__fsqrt_rn(u) > h) u = __int_as_float(__float_as_int(u) - 1);
    if (__fsqrt_rn(u) > h) u = __int_as_float(__float_as_int(u) - 1);
    float un = __int_as_float(__float_as_int(u) + 1);
    if (__fsqrt_rn(un) <= h) {
        u = un; un = __int_as_float(__float_as_int(u) + 1);
        if (__fsqrt_rn(un) <= h) {
            u = un; un = __int_as_float(__float_as_int(u) + 1);
            if (__fsqrt_rn(un) <= h) u = un;
        }
    }
    g_aux[i] = make_float2(u, __frcp_rn(h));
}

// ------- kernel 3: rank sort, TWO cells per warp (2x MLP on load chain) -----
__global__ void sortK() {
    int base = ((blockIdx.x * blockDim.x + threadIdx.x) >> 5) * 2;
    if (base >= NUM_CELLS) return;
    int lane = threadIdx.x & 31;
    int w0 = base, w1 = base + 1;

    int m0 = min(g_cellCount[w0], KSLOT);
    int m1 = min(g_cellCount[w1], KSLOT);

    float4 e0 = make_float4(0.f, 0.f, 0.f, 0.f);
    float4 e1 = make_float4(0.f, 0.f, 0.f, 0.f);
    int idx0 = 0x7fffffff, idx1 = 0x7fffffff;
    if (lane < m0) { e0 = g_cellListP[w0 * CAP + lane]; idx0 = __float_as_int(e0.x); }
    if (lane < m1) { e1 = g_cellListP[w1 * CAP + lane]; idx1 = __float_as_int(e1.x); }

    int r0 = 0, r1 = 0;
    for (int j = 0; j < m0; j++) r0 += (__shfl_sync(FULLM, idx0, j) < idx0);
    for (int j = 0; j < m1; j++) r1 += (__shfl_sync(FULLM, idx1, j) < idx1);

    if (lane == 0) { g_tabCnt[w0] = m0; g_tabCnt[w1] = m1; }
    if (lane < m0) g_tab[w0 * KSLOT + r0] = e0;
    if (lane < m1) g_tab[w1 * KSLOT + r1] = e1;
}

__device__ __forceinline__ float sqrt_approx(float x) {
    float r;
    asm("sqrt.approx.f32 %0, %1;" : "=f"(r) : "f"(x));
    return r;
}

// ------- kernel 4: warp-per-cell neighbor search (R8 proven form) ------------
__global__ void searchK(float* __restrict__ out) {
    int w = (blockIdx.x * blockDim.x + threadIdx.x) >> 5;   // warp id = cell
    if (w >= NUM_CELLS) return;
    int lane = threadIdx.x & 31;

    // ---- stencil setup (once per cell) ----
    int c = NUM_CELLS, m = 0;
    if (lane < 9) {
        int dxo = lane / 3 - 1;
        int dyo = lane % 3 - 1;
        int cc = w + dxo + GRIDW * dyo;
        cc = min(max(cc, 0), NUM_CELLS);
        c = cc;
        m = g_tabCnt[cc];
    }
    int incl = m;
#pragma unroll
    for (int d = 1; d < 16; d <<= 1) {
        int v = __shfl_up_sync(FULLM, incl, d);
        if (lane >= d) incl += v;
    }
    int pref = incl - m;
    int T = __shfl_sync(FULLM, incl, 8);

    int qcnt = __shfl_sync(FULLM, m, 4);      // center cell = this cell's queries
    if (qcnt == 0) return;

    int p1 = __shfl_sync(FULLM, pref, 1);
    int p2 = __shfl_sync(FULLM, pref, 2);
    int p3 = __shfl_sync(FULLM, pref, 3);
    int p4 = __shfl_sync(FULLM, pref, 4);
    int p5 = __shfl_sync(FULLM, pref, 5);
    int p6 = __shfl_sync(FULLM, pref, 6);
    int p7 = __shfl_sync(FULLM, pref, 7);
    int p8 = __shfl_sync(FULLM, pref, 8);

    // ---- query data (direct load) ----
    float4 qe = make_float4(0.f, 0.f, 0.f, 0.f);
    float tL = 0.0f, rhL = 0.0f;
    int qidl = 0;
    if (lane < qcnt) {
        qe = g_cellListP[w * CAP + lane];
        qidl = __float_as_int(qe.x);
        float2 aux = __ldg(&g_aux[qidl]);     // parallel prefetch {t, 1/h}
        tL = aux.x; rhL = aux.y;
    }

    // ---- preload candidates (chunks 0,1 cover T <= 64) ----
    float4 e0 = make_float4(0.f, 0.f, 0.f, 0.f);
    float4 e1 = make_float4(0.f, 0.f, 0.f, 0.f);
    bool act0 = lane < T;
    {
        int t = lane;
        int o = (t >= p1) + (t >= p2) + (t >= p3) + (t >= p4) +
                (t >= p5) + (t >= p6) + (t >= p7) + (t >= p8);
        int cc = __shfl_sync(FULLM, c, o);
        int po = __shfl_sync(FULLM, pref, o);
        if (act0) e0 = g_tab[cc * KSLOT + (t - po)];
    }
    bool act1 = (lane + 32) < T;
    if (T > 32) {
        int t = lane + 32;
        int o = (t >= p1) + (t >= p2) + (t >= p3) + (t >= p4) +
                (t >= p5) + (t >= p6) + (t >= p7) + (t >= p8);
        int cc = __shfl_sync(FULLM, c, o);
        int po = __shfl_sync(FULLM, pref, o);
        if (act1) e1 = g_tab[cc * KSLOT + (t - po)];
    }
    float n0 = (float)__float_as_int(e0.x);
    float n1 = (float)__float_as_int(e1.x);

    float* outN = out;                              // (N, 64) neighbor indices
    float* outC = out + (size_t)NP * MAXN;          // (N,)    counts
    float* outR = outC + NP;                        // (N, 64) radial

    int myCnt = 0;                                  // this lane's query count

    // ---- per-query loop ----
    for (int q = 0; q < qcnt; q++) {
        float px = __shfl_sync(FULLM, qe.y, q);
        float py = __shfl_sync(FULLM, qe.z, q);
        float tq = __shfl_sync(FULLM, tL, q);
        float rh = __shfl_sync(FULLM, rhL, q);
        int  qid = __shfl_sync(FULLM, qidl, q);
        int  rbase = qid << 6;                      // 32-bit row offset
        float* pN = outN + rbase;
        float* pR = outR + rbase;

        int cnt;
        // chunk 0
        {
            float dx = __fsub_rn(e0.y, px);
            float dy = __fsub_rn(e0.z, py);
            float d2 = __fadd_rn(__fmul_rn(dx, dx), __fmul_rn(dy, dy));
            bool ok = act0 && (d2 <= tq);           // exact selection via threshold
            unsigned bal = __ballot_sync(FULLM, ok);
            int slot = __popc(bal & ((1u << lane) - 1u));
            if (ok) {
                __stcs(&pN[slot], n0);
                __stcs(&pR[slot], __fmul_rn(sqrt_approx(d2), rh));
            }
            cnt = __popc(bal);
        }
        // chunk 1
        if (T > 32) {
            float dx = __fsub_rn(e1.y, px);
            float dy = __fsub_rn(e1.z, py);
            float d2 = __fadd_rn(__fmul_rn(dx, dx), __fmul_rn(dy, dy));
            bool ok = act1 && (d2 <= tq);
            unsigned bal = __ballot_sync(FULLM, ok);
            int slot = cnt + __popc(bal & ((1u << lane) - 1u));
            if (ok) {
                __stcs(&pN[slot], n1);
                __stcs(&pR[slot], __fmul_rn(sqrt_approx(d2), rh));
            }
            cnt += __popc(bal);
        }
        // rare: T > 64
        for (int tb = 64; tb < T; tb += 32) {
            int t = tb + lane;
            bool act = t < T;
            int o = (t >= p1) + (t >= p2) + (t >= p3) + (t >= p4) +
                    (t >= p5) + (t >= p6) + (t >= p7) + (t >= p8);
            int cc = __shfl_sync(FULLM, c, o);
            int po = __shfl_sync(FULLM, pref, o);
            float nidx = 0.0f, d2 = 0.0f;
            bool ok = false;
            if (act) {
                float4 e = g_tab[cc * KSLOT + (t - po)];
                float dx = __fsub_rn(e.y, px);
                float dy = __fsub_rn(e.z, py);
                d2 = __fadd_rn(__fmul_rn(dx, dx), __fmul_rn(dy, dy));
                nidx = (float)__float_as_int(e.x);
                ok = d2 <= tq;
            }
            unsigned bal = __ballot_sync(FULLM, ok);
            int slot = cnt + __popc(bal & ((1u << lane) - 1u));
            if (ok && slot < MAXN) {
                __stcs(&pN[slot], nidx);
                __stcs(&pR[slot], __fmul_rn(sqrt_approx(d2), rh));
            }
            cnt += __popc(bal);
        }
        // tail fill: unrolled two predicated steps (tail length <= 64)
        int start = min(cnt, MAXN);
        int k0 = start + lane;
        if (k0 < MAXN) {
            __stcs(&pN[k0], -1.0f);
            __stcs(&pR[k0], 0.0f);
        }
        int k1 = k0 + 32;
        if (k1 < MAXN) {
            __stcs(&pN[k1], -1.0f);
            __stcs(&pR[k1], 0.0f);
        }
        if (q == lane) myCnt = cnt;                 // defer count store
    }
    if (lane < qcnt) __stcs(&outC[qidl], (float)myCnt);
}

// ---------------- launch ------------------------------------------------------
extern "C" void kernel_launch(void* const* d_in, const int* in_sizes, int n_in,
                              void* d_out, int out_size) {
    const float* pos = (const float*)d_in[0];   // (N, 2) float32
    const float* sup = (const float*)d_in[1];   // (N,)   float32
    float* out = (float*)d_out;

    initRedK<<<256, 256>>>(pos, sup);
    binK<<<NP / 256, 256>>>(pos, sup);
    sortK<<<(NUM_CELLS / 2 * 32) / 256, 256>>>();
    searchK<<<(NUM_CELLS * 32) / 256, 256>>>(out);
}